// round 14
// baseline (speedup 1.0000x reference)
#include <cuda_runtime.h>
#include <cstdint>

// ---------------- problem constants ----------------
#define NN 50000
#define NE 800000
#define DD 300
#define NG 256
#define NL 5
#define F4C 75            // DD/4
#define NPADB 320         // n padded: 4 n-warps * 80

// ---------------- GEMM tiling: 64 x 320 tile, 256 thr ----------------------
#define BKT 32            // k per tile
#define NKT 10            // 320/32
#define NT_W 10           // n-frags per warp (80/8)
#define MT_W 2            // m-frags per warp (32/16)
#define W_AH 0
#define W_AL 1280         // A plane: 64 rows * 20 words
#define W_B  2560
#define W_STAGE 12800     // 2560 + 10240
#define SMEM_BYTES (2*W_STAGE*4)   // 102400

// ---------------- scratch ----------------
__device__ float g_x   [NN * DD];
__device__ float g_h   [NN * DD];
__device__ float g_hid [NN * DD];
__device__ float g_e   [(long long)NE * DD];     // 960 MB (dst-sorted rows)
__device__ uint4 g_wb  [11 * NKT * NPADB * 8];   // bf16 frag-major weights
__device__ int   g_cnt_i [NN];
__device__ int   g_rowptr[NN + 1];
__device__ int   g_cursor[NN];
__device__ int   g_slot  [NE];
__device__ int   g_srcs  [NE];
__device__ float g_pool [NG * DD];
__device__ float g_pool2[NG * DD];
__device__ float g_cnt  [NG];

enum { A_GMEM = 0, A_NODE2 = 1, A_EDGE3 = 2 };
enum { E_BIAS = 0, E_RELU = 1, E_EMB = 2 };

// ---------------- helpers ----------------
__device__ __forceinline__ uint32_t smem_u32(const void* p) {
    uint32_t a;
    asm("{ .reg .u64 t; cvta.to.shared.u64 t, %1; cvt.u32.u64 %0, t; }" : "=r"(a) : "l"(p));
    return a;
}
__device__ __forceinline__ uint16_t bf16r(float f) {
    uint16_t u; asm("cvt.rn.bf16.f32 %0, %1;" : "=h"(u) : "f"(f)); return u;
}
__device__ __forceinline__ float bf2f(uint16_t u) {
    return __uint_as_float(((uint32_t)u) << 16);
}
__device__ __forceinline__ uint32_t packbf(uint16_t lo, uint16_t hi) {
    return ((uint32_t)hi << 16) | lo;
}
#define CP_ASYNC16(dst, src) \
    asm volatile("cp.async.ca.shared.global [%0], [%1], 16;" :: "r"(dst), "l"(src) : "memory")
#define CP_COMMIT()  asm volatile("cp.async.commit_group;" ::: "memory")
#define CP_WAIT0()   asm volatile("cp.async.wait_group 0;" ::: "memory")

__device__ __forceinline__ void mma_bf16(float* c, uint32_t a0, uint32_t a1, uint32_t a2,
                                         uint32_t a3, uint32_t b0, uint32_t b1) {
    asm volatile(
        "mma.sync.aligned.m16n8k16.row.col.f32.bf16.bf16.f32 "
        "{%0,%1,%2,%3}, {%4,%5,%6,%7}, {%8,%9}, {%0,%1,%2,%3};"
        : "+f"(c[0]), "+f"(c[1]), "+f"(c[2]), "+f"(c[3])
        : "r"(a0), "r"(a1), "r"(a2), "r"(a3), "r"(b0), "r"(b1));
}

// ---------------- weight prep: frag-major bf16 hi/lo chunks ----------------
__global__ void prep_w(const float* __restrict__ W, int mat)
{
    int idx = blockIdx.x * 256 + threadIdx.x;
    if (idx >= NKT * NPADB * 8) return;
    int kt = idx / (NPADB * 8);
    int r  = idx - kt * NPADB * 8;
    int n  = r >> 3;
    int slot = r & 7;
    int ks = ((slot ^ ((n & 1) * 4)) >> 2) & 1;
    int tg = slot & 3;
    int k0 = kt * 32 + ks * 16 + 2 * tg;

    float v[4];
#pragma unroll
    for (int j = 0; j < 4; j++) {
        int k = k0 + (j >> 1) * 8 + (j & 1);
        v[j] = (n < DD && k < DD) ? W[k * DD + n] : 0.f;
    }
    uint16_t h[4], l[4];
#pragma unroll
    for (int j = 0; j < 4; j++) {
        h[j] = bf16r(v[j]);
        l[j] = bf16r(v[j] - bf2f(h[j]));
    }
    g_wb[(long long)mat * NKT * NPADB * 8 + idx] =
        make_uint4(packbf(h[0],h[1]), packbf(h[2],h[3]), packbf(l[0],l[1]), packbf(l[2],l[3]));
}

// ---------------- A tile generation (64 rows, 256 threads) ------------------
template<int ASRC>
__device__ __forceinline__ void gen_a(uint4& oh, uint4& ol, int row0, int k0t, int M,
    const float* __restrict__ A, const float* __restrict__ s0,
    const float* __restrict__ s1, const float* __restrict__ aW1,
    const float* __restrict__ ab1, int tid)
{
    int row = tid >> 2, c4 = tid & 3;
    int mg = row0 + row;
    float f[8];
#pragma unroll
    for (int j = 0; j < 8; j++) f[j] = 0.f;
    if (mg < M) {
#pragma unroll
        for (int half = 0; half < 2; half++) {
            int kg = k0t + c4 * 8 + half * 4;
            if (kg < DD) {
                if (ASRC == A_GMEM) {
                    float4 v = *(const float4*)&A[(long long)mg * DD + kg];
                    f[half*4+0] = v.x; f[half*4+1] = v.y; f[half*4+2] = v.z; f[half*4+3] = v.w;
                } else if (ASRC == A_NODE2) {
                    float a0 = __ldg(&s0[mg]), a1 = __ldg(&s1[mg]);
                    float4 w0 = *(const float4*)&aW1[kg];
                    float4 w1 = *(const float4*)&aW1[DD + kg];
                    float4 bb = *(const float4*)&ab1[kg];
                    f[half*4+0] = fmaxf(a0*w0.x + a1*w1.x + bb.x, 0.f);
                    f[half*4+1] = fmaxf(a0*w0.y + a1*w1.y + bb.y, 0.f);
                    f[half*4+2] = fmaxf(a0*w0.z + a1*w1.z + bb.z, 0.f);
                    f[half*4+3] = fmaxf(a0*w0.w + a1*w1.w + bb.w, 0.f);
                } else {
                    float e0 = __ldg(&s0[mg*3+0]), e1 = __ldg(&s0[mg*3+1]), e2 = __ldg(&s0[mg*3+2]);
                    float4 w0 = *(const float4*)&aW1[kg];
                    float4 w1 = *(const float4*)&aW1[DD + kg];
                    float4 w2 = *(const float4*)&aW1[2*DD + kg];
                    float4 bb = *(const float4*)&ab1[kg];
                    f[half*4+0] = fmaxf(e0*w0.x + e1*w1.x + e2*w2.x + bb.x, 0.f);
                    f[half*4+1] = fmaxf(e0*w0.y + e1*w1.y + e2*w2.y + bb.y, 0.f);
                    f[half*4+2] = fmaxf(e0*w0.z + e1*w1.z + e2*w2.z + bb.z, 0.f);
                    f[half*4+3] = fmaxf(e0*w0.w + e1*w1.w + e2*w2.w + bb.w, 0.f);
                }
            }
        }
    }
    uint16_t h[8], l[8];
#pragma unroll
    for (int j = 0; j < 8; j++) {
        h[j] = bf16r(f[j]);
        l[j] = bf16r(f[j] - bf2f(h[j]));
    }
    oh = make_uint4(packbf(h[0],h[1]), packbf(h[2],h[3]), packbf(h[4],h[5]), packbf(h[6],h[7]));
    ol = make_uint4(packbf(l[0],l[1]), packbf(l[2],l[3]), packbf(l[4],l[5]), packbf(l[6],l[7]));
}

__device__ __forceinline__ void sts_a(uint32_t* sw, const uint4& oh, const uint4& ol, int tid)
{
    int row = tid >> 2, c4 = tid & 3;
    int w = row * 20 + c4 * 4;
    *(uint4*)(sw + W_AH + w) = oh;
    *(uint4*)(sw + W_AL + w) = ol;
}

__device__ __forceinline__ void issue_b(uint32_t* sw, const uint4* __restrict__ Bt,
                                        int kt, int tid)
{
    const uint4* src = Bt + (long long)kt * NPADB * 8;
    uint32_t dbase = smem_u32(sw + W_B);
#pragma unroll
    for (int i = 0; i < 10; i++) {
        int idx = tid + i * 256;
        CP_ASYNC16(dbase + idx * 16, src + idx);
    }
}

// ============================================================
// bf16x3 mma.sync GEMM: CTA 64x320, 256 threads, 8 warps (2m x 4n).
// Pass-reordered inner loop: B frags preloaded to regs, the 3 bf16x3
// passes run outermost so same-accumulator MMAs are 20 apart.
// ============================================================
template<int ASRC, int EPI, bool PERM>
__global__ __launch_bounds__(256, 1)
void mma_gemm(const float* __restrict__ A,
              const float* __restrict__ s0, const float* __restrict__ s1,
              const float* __restrict__ aW1, const float* __restrict__ ab1,
              const uint4* __restrict__ Bt, const float* __restrict__ bias,
              const float* __restrict__ emb, const int* __restrict__ zidx,
              const int* __restrict__ perm,
              float* __restrict__ Out, int M)
{
    extern __shared__ uint32_t sw[];
    const int tid  = threadIdx.x;
    const int lane = tid & 31;
    const int wid  = tid >> 5;
    const int g    = lane >> 2;
    const int tg   = lane & 3;
    const int wm   = wid >> 2;       // 0..1  -> rows wm*32
    const int wn   = wid & 3;        // 0..3  -> cols wn*80
    const int row0 = blockIdx.x * 64;

    float acc[MT_W][NT_W][4];
#pragma unroll
    for (int mt = 0; mt < MT_W; mt++)
#pragma unroll
        for (int nt = 0; nt < NT_W; nt++)
#pragma unroll
            for (int i = 0; i < 4; i++) acc[mt][nt][i] = 0.f;

    {
        uint4 oh, ol;
        gen_a<ASRC>(oh, ol, row0, 0, M, A, s0, s1, aW1, ab1, tid);
        sts_a(sw, oh, ol, tid);
        issue_b(sw, Bt, 0, tid);
        CP_COMMIT();
        CP_WAIT0();
    }
    __syncthreads();

    for (int t = 0; t < NKT; t++) {
        uint32_t* cur = sw + (t & 1) * W_STAGE;
        uint32_t* nxt = sw + ((t & 1) ^ 1) * W_STAGE;
        const bool more = (t + 1 < NKT);

        uint4 oh, ol;
        if (more) {
            issue_b(nxt, Bt, t + 1, tid);
            CP_COMMIT();
            gen_a<ASRC>(oh, ol, row0, (t + 1) * BKT, M, A, s0, s1, aW1, ab1, tid);
        }

        const uint32_t* AH = cur + W_AH;
        const uint32_t* AL = cur + W_AL;
        const uint32_t* BB = cur + W_B;
#pragma unroll
        for (int ks = 0; ks < 2; ks++) {
            uint32_t aH[MT_W][4], aL[MT_W][4];
#pragma unroll
            for (int mt = 0; mt < MT_W; mt++) {
                int rbase = (wm * 32 + mt * 16 + g) * 20 + ks * 8 + tg;
                aH[mt][0] = AH[rbase];       aH[mt][1] = AH[rbase + 160];
                aH[mt][2] = AH[rbase + 4];   aH[mt][3] = AH[rbase + 164];
                aL[mt][0] = AL[rbase];       aL[mt][1] = AL[rbase + 160];
                aL[mt][2] = AL[rbase + 4];   aL[mt][3] = AL[rbase + 164];
            }
            const int slot = (ks * 4 + tg) ^ ((g & 1) * 4);

            // preload all B frags for this k-half into registers
            uint4 bv[NT_W];
#pragma unroll
            for (int nt = 0; nt < NT_W; nt++) {
                int n = wn * 80 + nt * 8 + g;
                bv[nt] = *(const uint4*)(BB + (n * 8 + slot) * 4);
            }

            // pass 1: hi * hi
#pragma unroll
            for (int nt = 0; nt < NT_W; nt++)
#pragma unroll
                for (int mt = 0; mt < MT_W; mt++)
                    mma_bf16(acc[mt][nt], aH[mt][0], aH[mt][1], aH[mt][2], aH[mt][3],
                             bv[nt].x, bv[nt].y);
            // pass 2: lo * hi
#pragma unroll
            for (int nt = 0; nt < NT_W; nt++)
#pragma unroll
                for (int mt = 0; mt < MT_W; mt++)
                    mma_bf16(acc[mt][nt], aL[mt][0], aL[mt][1], aL[mt][2], aL[mt][3],
                             bv[nt].x, bv[nt].y);
            // pass 3: hi * lo
#pragma unroll
            for (int nt = 0; nt < NT_W; nt++)
#pragma unroll
                for (int mt = 0; mt < MT_W; mt++)
                    mma_bf16(acc[mt][nt], aH[mt][0], aH[mt][1], aH[mt][2], aH[mt][3],
                             bv[nt].z, bv[nt].w);
        }

        if (more) {
            sts_a(nxt, oh, ol, tid);
            CP_WAIT0();
        }
        __syncthreads();
    }

    // ---- epilogue ----
#pragma unroll
    for (int mt = 0; mt < MT_W; mt++) {
        int r0 = row0 + wm * 32 + mt * 16 + g;
        int r1 = r0 + 8;
        const float* er0 = nullptr;
        const float* er1 = nullptr;
        if (EPI == E_EMB) {
            if (r0 < M) er0 = emb + (long long)__ldg(&zidx[r0]) * DD;
            if (r1 < M) er1 = emb + (long long)__ldg(&zidx[r1]) * DD;
        }
        long long o0 = 0, o1 = 0;
        if (r0 < M) o0 = (long long)(PERM ? __ldg(&perm[r0]) : r0) * DD;
        if (r1 < M) o1 = (long long)(PERM ? __ldg(&perm[r1]) : r1) * DD;
#pragma unroll
        for (int nt = 0; nt < NT_W; nt++) {
            int col = wn * 80 + nt * 8 + tg * 2;
            if (col >= DD) continue;
            float2 bb = *(const float2*)&bias[col];
            if (r0 < M) {
                float2 o = make_float2(acc[mt][nt][0] + bb.x, acc[mt][nt][1] + bb.y);
                if (EPI == E_EMB) { float2 e = *(const float2*)&er0[col]; o.x += e.x; o.y += e.y; }
                if (EPI == E_RELU) { o.x = fmaxf(o.x, 0.f); o.y = fmaxf(o.y, 0.f); }
                *(float2*)&Out[o0 + col] = o;
            }
            if (r1 < M) {
                float2 o = make_float2(acc[mt][nt][2] + bb.x, acc[mt][nt][3] + bb.y);
                if (EPI == E_EMB) { float2 e = *(const float2*)&er1[col]; o.x += e.x; o.y += e.y; }
                if (EPI == E_RELU) { o.x = fmaxf(o.x, 0.f); o.y = fmaxf(o.y, 0.f); }
                *(float2*)&Out[o1 + col] = o;
            }
        }
    }
}

// ---------------- CSR build -------------------------------------------------
__global__ void zero_cnt()
{
    int i = blockIdx.x * 256 + threadIdx.x;
    if (i < NN) g_cnt_i[i] = 0;
}
__global__ void count_k(const int* __restrict__ ei)
{
    int e = blockIdx.x * 256 + threadIdx.x;
    if (e < NE) atomicAdd(&g_cnt_i[__ldg(ei + NE + e)], 1);
}
__global__ void scan_k()
{
    __shared__ int sm[1024];
    __shared__ int carry;
    int t = threadIdx.x;
    if (t == 0) carry = 0;
    __syncthreads();
    for (int base = 0; base < NN; base += 1024) {
        int i = base + t;
        int v = (i < NN) ? g_cnt_i[i] : 0;
        sm[t] = v;
        __syncthreads();
        for (int off = 1; off < 1024; off <<= 1) {
            int u = (t >= off) ? sm[t - off] : 0;
            __syncthreads();
            sm[t] += u;
            __syncthreads();
        }
        int exc = sm[t] - v + carry;
        if (i < NN) { g_rowptr[i] = exc; g_cursor[i] = exc; }
        __syncthreads();
        if (t == 1023) carry += sm[1023];
        __syncthreads();
    }
    if (t == 0) g_rowptr[NN] = carry;
}
__global__ void scatter_k(const int* __restrict__ ei)
{
    int e = blockIdx.x * 256 + threadIdx.x;
    if (e >= NE) return;
    int d = __ldg(ei + NE + e);
    int pos = atomicAdd(&g_cursor[d], 1);
    g_slot[e] = pos;
    g_srcs[pos] = __ldg(ei + e);
}

// ---------------- message pass: h[d] = x[d] + sum relu(x[src]+e) -----------
__global__ __launch_bounds__(96)
void msg_csr()
{
    int d = blockIdx.x;
    int t = threadIdx.x;
    if (t >= F4C) return;
    int beg = g_rowptr[d];
    int end = g_rowptr[d + 1];
    const float4* E = (const float4*)g_e;
    const float4* X = (const float4*)g_x;
    float4 acc = X[(long long)d * F4C + t];
    for (int j = beg; j < end; j++) {
        int s = __ldg(&g_srcs[j]);
        float4 ev = __ldcs(E + (long long)j * F4C + t);
        float4 xv = __ldg(X + (long long)s * F4C + t);
        acc.x += fmaxf(ev.x + xv.x, 0.f);
        acc.y += fmaxf(ev.y + xv.y, 0.f);
        acc.z += fmaxf(ev.z + xv.z, 0.f);
        acc.w += fmaxf(ev.w + xv.w, 0.f);
    }
    ((float4*)g_h)[(long long)d * F4C + t] = acc;
}

// ---------------- x := LN(x + relu(h2)) ------------------------------------
__global__ void ln_kernel(const float* __restrict__ g, const float* __restrict__ b)
{
    int warp = threadIdx.x >> 5;
    int lane = threadIdx.x & 31;
    int row  = blockIdx.x * 8 + warp;
    if (row >= NN) return;
    const float* xr = g_x + (long long)row * DD;
    const float* hr = g_h + (long long)row * DD;

    float v[10];
    float s = 0.f;
#pragma unroll
    for (int i = 0; i < 10; i++) {
        int j = lane + 32 * i;
        if (j < DD) { v[i] = xr[j] + fmaxf(hr[j], 0.f); s += v[i]; }
        else          v[i] = 0.f;
    }
#pragma unroll
    for (int o = 16; o; o >>= 1) s += __shfl_xor_sync(0xffffffffu, s, o);
    float mu = s * (1.f / DD);

    float vs = 0.f;
#pragma unroll
    for (int i = 0; i < 10; i++) {
        int j = lane + 32 * i;
        if (j < DD) { float d = v[i] - mu; vs += d * d; }
    }
#pragma unroll
    for (int o = 16; o; o >>= 1) vs += __shfl_xor_sync(0xffffffffu, vs, o);
    float rstd = rsqrtf(vs * (1.f / DD) + 1e-5f);

    float* xw = g_x + (long long)row * DD;
#pragma unroll
    for (int i = 0; i < 10; i++) {
        int j = lane + 32 * i;
        if (j < DD) xw[j] = (v[i] - mu) * rstd * g[j] + b[j];
    }
}

// ---------------- pooling ---------------------------------------------------
__global__ void zero_pool()
{
    int idx = blockIdx.x * 256 + threadIdx.x;
    if (idx < NG * DD) g_pool[idx] = 0.f;
    if (idx < NG)      g_cnt[idx]  = 0.f;
}
__global__ void pool_accum(const int* __restrict__ batch)
{
    int idx = blockIdx.x * 256 + threadIdx.x;
    if (idx >= NN * F4C) return;
    int n = idx / F4C;
    int c = idx - n * F4C;
    int bg = __ldg(batch + n);
    float4 xv = ((const float4*)g_x)[idx];
    float* p = g_pool + bg * DD + c * 4;
    atomicAdd(p + 0, xv.x);
    atomicAdd(p + 1, xv.y);
    atomicAdd(p + 2, xv.z);
    atomicAdd(p + 3, xv.w);
    if (c == 0) atomicAdd(&g_cnt[bg], 1.f);
}
__global__ void pool_div()
{
    int idx = blockIdx.x * 256 + threadIdx.x;
    if (idx < NG * DD) g_pool[idx] /= fmaxf(g_cnt[idx / DD], 1.f);
}
__global__ void small_gemm(const float* __restrict__ A, const float* __restrict__ W,
                           const float* __restrict__ bias, float* __restrict__ O,
                           int K, int Nout)
{
    int j = blockIdx.x * blockDim.x + threadIdx.x;
    int g = blockIdx.y;
    if (j >= Nout) return;
    float s = bias[j];
    const float* ar = A + g * K;
    for (int k = 0; k < K; k++)
        s = fmaf(__ldg(ar + k), __ldg(&W[k * Nout + j]), s);
    O[g * Nout + j] = s;
}

// ============================================================
extern "C" void kernel_launch(void* const* d_in, const int* in_sizes, int n_in,
                              void* d_out, int out_size)
{
    const int*   z       = (const int*)  d_in[0];
    const float* chir    = (const float*)d_in[1];
    const float* fc      = (const float*)d_in[2];
    const int*   ei      = (const int*)  d_in[3];
    const float* ea      = (const float*)d_in[4];
    const int*   batch   = (const int*)  d_in[5];
    const float* atom_emb= (const float*)d_in[6];
    const float* nap_W1  = (const float*)d_in[7];
    const float* nap_b1  = (const float*)d_in[8];
    const float* nap_W2  = (const float*)d_in[9];
    const float* nap_b2  = (const float*)d_in[10];
    const float* ee_W1   = (const float*)d_in[11];
    const float* ee_b1   = (const float*)d_in[12];
    const float* ee_W2   = (const float*)d_in[13];
    const float* ee_b2   = (const float*)d_in[14];
    const float* gine_W1 = (const float*)d_in[15];
    const float* gine_b1 = (const float*)d_in[16];
    const float* gine_W2 = (const float*)d_in[17];
    const float* gine_b2 = (const float*)d_in[18];
    const float* ln_g    = (const float*)d_in[19];
    const float* ln_b    = (const float*)d_in[20];
    const float* pool_W  = (const float*)d_in[21];
    const float* pool_b  = (const float*)d_in[22];
    const float* proj_W  = (const float*)d_in[23];
    const float* proj_b  = (const float*)d_in[24];

    float *px, *ph, *phid, *pe, *ppool, *ppool2;
    uint4 *pwb;
    int   *pslot;
    cudaGetSymbolAddress((void**)&px,    g_x);
    cudaGetSymbolAddress((void**)&ph,    g_h);
    cudaGetSymbolAddress((void**)&phid,  g_hid);
    cudaGetSymbolAddress((void**)&pe,    g_e);
    cudaGetSymbolAddress((void**)&pwb,   g_wb);
    cudaGetSymbolAddress((void**)&pslot, g_slot);
    cudaGetSymbolAddress((void**)&ppool, g_pool);
    cudaGetSymbolAddress((void**)&ppool2,g_pool2);

    cudaFuncSetAttribute(mma_gemm<A_NODE2, E_EMB,  false>, cudaFuncAttributeMaxDynamicSharedMemorySize, SMEM_BYTES);
    cudaFuncSetAttribute(mma_gemm<A_EDGE3, E_BIAS, true >, cudaFuncAttributeMaxDynamicSharedMemorySize, SMEM_BYTES);
    cudaFuncSetAttribute(mma_gemm<A_GMEM,  E_RELU, false>, cudaFuncAttributeMaxDynamicSharedMemorySize, SMEM_BYTES);
    cudaFuncSetAttribute(mma_gemm<A_GMEM,  E_BIAS, false>, cudaFuncAttributeMaxDynamicSharedMemorySize, SMEM_BYTES);

    const int gNode = (NN + 63) / 64;         // 782
    const int gEdge = NE / 64;                // 12500
    const int gNNv  = (NN * F4C + 255) / 256;
    const int gLN   = (NN + 7) / 8;
    const int gPool = (NG * DD + 255) / 256;
    const int gPrep = (NKT * NPADB * 8 + 255) / 256;
    const int gNNi  = (NN + 255) / 256;
    const int gNEi  = (NE + 255) / 256;
    const long long WSZ = (long long)NKT * NPADB * 8;

    // Launch order keeps node GEMM as 4th launch (ncu window).
    prep_w<<<gPrep, 256>>>(nap_W2, 0);                                  // 1
    prep_w<<<gPrep, 256>>>(ee_W2, 1);                                   // 2
    zero_cnt<<<gNNi, 256>>>();                                          // 3
    mma_gemm<A_NODE2, E_EMB, false><<<gNode, 256, SMEM_BYTES>>>(        // 4 <- profiled
        nullptr, chir, fc, nap_W1, nap_b1,
        pwb + 0 * WSZ, nap_b2, atom_emb, z, nullptr, px, NN);

    // CSR build
    count_k<<<gNEi, 256>>>(ei);
    scan_k<<<1, 1024>>>();
    scatter_k<<<gNEi, 256>>>(ei);

    // remaining weight prep
    for (int i = 0; i < NL; i++) {
        prep_w<<<gPrep, 256>>>(gine_W1 + (long long)i * DD * DD, 2 + i);
        prep_w<<<gPrep, 256>>>(gine_W2 + (long long)i * DD * DD, 7 + i);
    }

    // edge emb (dst-sorted rows)
    mma_gemm<A_EDGE3, E_BIAS, true><<<gEdge, 256, SMEM_BYTES>>>(
        nullptr, ea, nullptr, ee_W1, ee_b1,
        pwb + 1 * WSZ, ee_b2, nullptr, nullptr, pslot, pe, NE);

    // GINE layers
    for (int i = 0; i < NL; i++) {
        msg_csr<<<NN, 96>>>();
        mma_gemm<A_GMEM, E_RELU, false><<<gNode, 256, SMEM_BYTES>>>(
            ph, nullptr, nullptr, nullptr, nullptr,
            pwb + (2 + i) * WSZ, gine_b1 + i * DD, nullptr, nullptr, nullptr, phid, NN);
        mma_gemm<A_GMEM, E_BIAS, false><<<gNode, 256, SMEM_BYTES>>>(
            phid, nullptr, nullptr, nullptr, nullptr,
            pwb + (7 + i) * WSZ, gine_b2 + i * DD, nullptr, nullptr, nullptr, ph, NN);
        ln_kernel<<<gLN, 256>>>(ln_g + i * DD, ln_b + i * DD);
    }

    // pooling + projections
    zero_pool<<<gPool, 256>>>();
    pool_accum<<<gNNv, 256>>>(batch);
    pool_div<<<gPool, 256>>>();
    small_gemm<<<dim3(2, NG), 256>>>(ppool,  pool_W, pool_b, ppool2, DD, DD);
    small_gemm<<<dim3(3, NG), 256>>>(ppool2, proj_W, proj_b, (float*)d_out, DD, 600);
}

// round 16
// speedup vs baseline: 1.2199x; 1.2199x over previous
#include <cuda_runtime.h>
#include <cstdint>

// ---------------- problem constants ----------------
#define NN 50000
#define NE 800000
#define DD 300
#define NG 256
#define NL 5
#define F4C 75            // DD/4
#define NPADB 320         // n padded: 4 n-warps * 80

// ---------------- GEMM tiling: 64 x 320 tile, 256 thr, 2 CTAs/SM ----------
#define BKT 32
#define NKT 10
#define NT_W 10
#define MT_W 2
#define W_AH 0
#define W_AL 1280
#define W_B  2560
#define W_STAGE 12800
#define SMEM_BYTES (2*W_STAGE*4)   // 102400

// ---------------- scratch ----------------
__device__ float g_x   [NN * DD];
__device__ float g_h   [NN * DD];
__device__ float g_hid [NN * DD];
__device__ float g_e   [(long long)NE * DD];     // 960 MB (dst-sorted rows)
__device__ uint4 g_wb  [11 * NKT * NPADB * 8];   // bf16 frag-major weights
__device__ int   g_cnt_i [NN];
__device__ int   g_rowptr[NN + 1];
__device__ int   g_cursor[NN];
__device__ int   g_slot  [NE];
__device__ int   g_srcs  [NE];
__device__ float g_pool [NG * DD];
__device__ float g_pool2[NG * DD];
__device__ float g_cnt  [NG];

enum { A_GMEM = 0, A_NODE2 = 1, A_EDGE3 = 2 };
enum { E_BIAS = 0, E_RELU = 1, E_EMB = 2 };

// ---------------- helpers ----------------
__device__ __forceinline__ uint32_t smem_u32(const void* p) {
    uint32_t a;
    asm("{ .reg .u64 t; cvta.to.shared.u64 t, %1; cvt.u32.u64 %0, t; }" : "=r"(a) : "l"(p));
    return a;
}
__device__ __forceinline__ uint16_t bf16r(float f) {
    uint16_t u; asm("cvt.rn.bf16.f32 %0, %1;" : "=h"(u) : "f"(f)); return u;
}
__device__ __forceinline__ float bf2f(uint16_t u) {
    return __uint_as_float(((uint32_t)u) << 16);
}
__device__ __forceinline__ uint32_t packbf(uint16_t lo, uint16_t hi) {
    return ((uint32_t)hi << 16) | lo;
}
#define CP_ASYNC16(dst, src) \
    asm volatile("cp.async.ca.shared.global [%0], [%1], 16;" :: "r"(dst), "l"(src) : "memory")
#define CP_COMMIT()  asm volatile("cp.async.commit_group;" ::: "memory")
#define CP_WAIT0()   asm volatile("cp.async.wait_group 0;" ::: "memory")

__device__ __forceinline__ void mma_bf16(float* c, uint32_t a0, uint32_t a1, uint32_t a2,
                                         uint32_t a3, uint32_t b0, uint32_t b1) {
    asm volatile(
        "mma.sync.aligned.m16n8k16.row.col.f32.bf16.bf16.f32 "
        "{%0,%1,%2,%3}, {%4,%5,%6,%7}, {%8,%9}, {%0,%1,%2,%3};"
        : "+f"(c[0]), "+f"(c[1]), "+f"(c[2]), "+f"(c[3])
        : "r"(a0), "r"(a1), "r"(a2), "r"(a3), "r"(b0), "r"(b1));
}

// ---------------- weight prep: frag-major bf16 hi/lo chunks ----------------
__global__ void prep_w(const float* __restrict__ W, int mat)
{
    int idx = blockIdx.x * 256 + threadIdx.x;
    if (idx >= NKT * NPADB * 8) return;
    int kt = idx / (NPADB * 8);
    int r  = idx - kt * NPADB * 8;
    int n  = r >> 3;
    int slot = r & 7;
    int ks = ((slot ^ ((n & 1) * 4)) >> 2) & 1;
    int tg = slot & 3;
    int k0 = kt * 32 + ks * 16 + 2 * tg;

    float v[4];
#pragma unroll
    for (int j = 0; j < 4; j++) {
        int k = k0 + (j >> 1) * 8 + (j & 1);
        v[j] = (n < DD && k < DD) ? W[k * DD + n] : 0.f;
    }
    uint16_t h[4], l[4];
#pragma unroll
    for (int j = 0; j < 4; j++) {
        h[j] = bf16r(v[j]);
        l[j] = bf16r(v[j] - bf2f(h[j]));
    }
    g_wb[(long long)mat * NKT * NPADB * 8 + idx] =
        make_uint4(packbf(h[0],h[1]), packbf(h[2],h[3]), packbf(l[0],l[1]), packbf(l[2],l[3]));
}

// ---------------- A tile generation (64 rows, 256 threads) ------------------
template<int ASRC>
__device__ __forceinline__ void gen_a(uint4& oh, uint4& ol, int row0, int k0t, int M,
    const float* __restrict__ A, const float* __restrict__ s0,
    const float* __restrict__ s1, const float* __restrict__ aW1,
    const float* __restrict__ ab1, int tid)
{
    int row = tid >> 2, c4 = tid & 3;
    int mg = row0 + row;
    float f[8];
#pragma unroll
    for (int j = 0; j < 8; j++) f[j] = 0.f;
    if (mg < M) {
#pragma unroll
        for (int half = 0; half < 2; half++) {
            int kg = k0t + c4 * 8 + half * 4;
            if (kg < DD) {
                if (ASRC == A_GMEM) {
                    float4 v = *(const float4*)&A[(long long)mg * DD + kg];
                    f[half*4+0] = v.x; f[half*4+1] = v.y; f[half*4+2] = v.z; f[half*4+3] = v.w;
                } else if (ASRC == A_NODE2) {
                    float a0 = __ldg(&s0[mg]), a1 = __ldg(&s1[mg]);
                    float4 w0 = *(const float4*)&aW1[kg];
                    float4 w1 = *(const float4*)&aW1[DD + kg];
                    float4 bb = *(const float4*)&ab1[kg];
                    f[half*4+0] = fmaxf(a0*w0.x + a1*w1.x + bb.x, 0.f);
                    f[half*4+1] = fmaxf(a0*w0.y + a1*w1.y + bb.y, 0.f);
                    f[half*4+2] = fmaxf(a0*w0.z + a1*w1.z + bb.z, 0.f);
                    f[half*4+3] = fmaxf(a0*w0.w + a1*w1.w + bb.w, 0.f);
                } else {
                    float e0 = __ldg(&s0[mg*3+0]), e1 = __ldg(&s0[mg*3+1]), e2 = __ldg(&s0[mg*3+2]);
                    float4 w0 = *(const float4*)&aW1[kg];
                    float4 w1 = *(const float4*)&aW1[DD + kg];
                    float4 w2 = *(const float4*)&aW1[2*DD + kg];
                    float4 bb = *(const float4*)&ab1[kg];
                    f[half*4+0] = fmaxf(e0*w0.x + e1*w1.x + e2*w2.x + bb.x, 0.f);
                    f[half*4+1] = fmaxf(e0*w0.y + e1*w1.y + e2*w2.y + bb.y, 0.f);
                    f[half*4+2] = fmaxf(e0*w0.z + e1*w1.z + e2*w2.z + bb.z, 0.f);
                    f[half*4+3] = fmaxf(e0*w0.w + e1*w1.w + e2*w2.w + bb.w, 0.f);
                }
            }
        }
    }
    uint16_t h[8], l[8];
#pragma unroll
    for (int j = 0; j < 8; j++) {
        h[j] = bf16r(f[j]);
        l[j] = bf16r(f[j] - bf2f(h[j]));
    }
    oh = make_uint4(packbf(h[0],h[1]), packbf(h[2],h[3]), packbf(h[4],h[5]), packbf(h[6],h[7]));
    ol = make_uint4(packbf(l[0],l[1]), packbf(l[2],l[3]), packbf(l[4],l[5]), packbf(l[6],l[7]));
}

__device__ __forceinline__ void sts_a(uint32_t* sw, const uint4& oh, const uint4& ol, int tid)
{
    int row = tid >> 2, c4 = tid & 3;
    int w = row * 20 + c4 * 4;
    *(uint4*)(sw + W_AH + w) = oh;
    *(uint4*)(sw + W_AL + w) = ol;
}

__device__ __forceinline__ void issue_b(uint32_t* sw, const uint4* __restrict__ Bt,
                                        int kt, int tid)
{
    const uint4* src = Bt + (long long)kt * NPADB * 8;
    uint32_t dbase = smem_u32(sw + W_B);
#pragma unroll
    for (int i = 0; i < 10; i++) {
        int idx = tid + i * 256;
        CP_ASYNC16(dbase + idx * 16, src + idx);
    }
}

// ============================================================
// bf16 split mma.sync GEMM (R12-proven core).
// PASSES: 3 = full bf16x3; 2 = drop hi*lo pass (edge GEMM).
// ============================================================
template<int ASRC, int EPI, bool PERM, int PASSES>
__global__ __launch_bounds__(256, 2)
void mma_gemm(const float* __restrict__ A,
              const float* __restrict__ s0, const float* __restrict__ s1,
              const float* __restrict__ aW1, const float* __restrict__ ab1,
              const uint4* __restrict__ Bt, const float* __restrict__ bias,
              const float* __restrict__ emb, const int* __restrict__ zidx,
              const int* __restrict__ perm,
              float* __restrict__ Out, int M)
{
    extern __shared__ uint32_t sw[];
    const int tid  = threadIdx.x;
    const int lane = tid & 31;
    const int wid  = tid >> 5;
    const int g    = lane >> 2;
    const int tg   = lane & 3;
    const int wm   = wid >> 2;
    const int wn   = wid & 3;
    const int row0 = blockIdx.x * 64;

    float acc[MT_W][NT_W][4];
#pragma unroll
    for (int mt = 0; mt < MT_W; mt++)
#pragma unroll
        for (int nt = 0; nt < NT_W; nt++)
#pragma unroll
            for (int i = 0; i < 4; i++) acc[mt][nt][i] = 0.f;

    {
        uint4 oh, ol;
        gen_a<ASRC>(oh, ol, row0, 0, M, A, s0, s1, aW1, ab1, tid);
        sts_a(sw, oh, ol, tid);
        issue_b(sw, Bt, 0, tid);
        CP_COMMIT();
        CP_WAIT0();
    }
    __syncthreads();

    for (int t = 0; t < NKT; t++) {
        uint32_t* cur = sw + (t & 1) * W_STAGE;
        uint32_t* nxt = sw + ((t & 1) ^ 1) * W_STAGE;
        const bool more = (t + 1 < NKT);

        uint4 oh, ol;
        if (more) {
            issue_b(nxt, Bt, t + 1, tid);
            CP_COMMIT();
            gen_a<ASRC>(oh, ol, row0, (t + 1) * BKT, M, A, s0, s1, aW1, ab1, tid);
        }

        const uint32_t* AH = cur + W_AH;
        const uint32_t* AL = cur + W_AL;
        const uint32_t* BB = cur + W_B;
#pragma unroll
        for (int ks = 0; ks < 2; ks++) {
            uint32_t aH[MT_W][4], aL[MT_W][4];
#pragma unroll
            for (int mt = 0; mt < MT_W; mt++) {
                int rbase = (wm * 32 + mt * 16 + g) * 20 + ks * 8 + tg;
                aH[mt][0] = AH[rbase];       aH[mt][1] = AH[rbase + 160];
                aH[mt][2] = AH[rbase + 4];   aH[mt][3] = AH[rbase + 164];
                aL[mt][0] = AL[rbase];       aL[mt][1] = AL[rbase + 160];
                aL[mt][2] = AL[rbase + 4];   aL[mt][3] = AL[rbase + 164];
            }
            const int slot = (ks * 4 + tg) ^ ((g & 1) * 4);
#pragma unroll
            for (int nt = 0; nt < NT_W; nt++) {
                int n = wn * 80 + nt * 8 + g;
                uint4 b = *(const uint4*)(BB + (n * 8 + slot) * 4);
#pragma unroll
                for (int mt = 0; mt < MT_W; mt++) {
                    mma_bf16(acc[mt][nt], aH[mt][0], aH[mt][1], aH[mt][2], aH[mt][3], b.x, b.y);
                    mma_bf16(acc[mt][nt], aL[mt][0], aL[mt][1], aL[mt][2], aL[mt][3], b.x, b.y);
                    if (PASSES == 3)
                        mma_bf16(acc[mt][nt], aH[mt][0], aH[mt][1], aH[mt][2], aH[mt][3], b.z, b.w);
                }
            }
        }

        if (more) {
            sts_a(nxt, oh, ol, tid);
            CP_WAIT0();
        }
        __syncthreads();
    }

    // ---- epilogue ----
#pragma unroll
    for (int mt = 0; mt < MT_W; mt++) {
        int r0 = row0 + wm * 32 + mt * 16 + g;
        int r1 = r0 + 8;
        const float* er0 = nullptr;
        const float* er1 = nullptr;
        if (EPI == E_EMB) {
            if (r0 < M) er0 = emb + (long long)__ldg(&zidx[r0]) * DD;
            if (r1 < M) er1 = emb + (long long)__ldg(&zidx[r1]) * DD;
        }
        long long o0 = 0, o1 = 0;
        if (r0 < M) o0 = (long long)(PERM ? __ldg(&perm[r0]) : r0) * DD;
        if (r1 < M) o1 = (long long)(PERM ? __ldg(&perm[r1]) : r1) * DD;
#pragma unroll
        for (int nt = 0; nt < NT_W; nt++) {
            int col = wn * 80 + nt * 8 + tg * 2;
            if (col >= DD) continue;
            float2 bb = *(const float2*)&bias[col];
            if (r0 < M) {
                float2 o = make_float2(acc[mt][nt][0] + bb.x, acc[mt][nt][1] + bb.y);
                if (EPI == E_EMB) { float2 e = *(const float2*)&er0[col]; o.x += e.x; o.y += e.y; }
                if (EPI == E_RELU) { o.x = fmaxf(o.x, 0.f); o.y = fmaxf(o.y, 0.f); }
                *(float2*)&Out[o0 + col] = o;
            }
            if (r1 < M) {
                float2 o = make_float2(acc[mt][nt][2] + bb.x, acc[mt][nt][3] + bb.y);
                if (EPI == E_EMB) { float2 e = *(const float2*)&er1[col]; o.x += e.x; o.y += e.y; }
                if (EPI == E_RELU) { o.x = fmaxf(o.x, 0.f); o.y = fmaxf(o.y, 0.f); }
                *(float2*)&Out[o1 + col] = o;
            }
        }
    }
}

// ---------------- CSR build (R12-proven) -----------------------------------
__global__ void zero_cnt()
{
    int i = blockIdx.x * 256 + threadIdx.x;
    if (i < NN) g_cnt_i[i] = 0;
}
__global__ void count_k(const int* __restrict__ ei)
{
    int e = blockIdx.x * 256 + threadIdx.x;
    if (e < NE) atomicAdd(&g_cnt_i[__ldg(ei + NE + e)], 1);
}
__global__ void scan_k()
{
    __shared__ int sm[1024];
    __shared__ int carry;
    int t = threadIdx.x;
    if (t == 0) carry = 0;
    __syncthreads();
    for (int base = 0; base < NN; base += 1024) {
        int i = base + t;
        int v = (i < NN) ? g_cnt_i[i] : 0;
        sm[t] = v;
        __syncthreads();
        for (int off = 1; off < 1024; off <<= 1) {
            int u = (t >= off) ? sm[t - off] : 0;
            __syncthreads();
            sm[t] += u;
            __syncthreads();
        }
        int exc = sm[t] - v + carry;
        if (i < NN) { g_rowptr[i] = exc; g_cursor[i] = exc; }
        __syncthreads();
        if (t == 1023) carry += sm[1023];
        __syncthreads();
    }
    if (t == 0) g_rowptr[NN] = carry;
}
__global__ void scatter_k(const int* __restrict__ ei)
{
    int e = blockIdx.x * 256 + threadIdx.x;
    if (e >= NE) return;
    int d = __ldg(ei + NE + e);
    int pos = atomicAdd(&g_cursor[d], 1);
    g_slot[e] = pos;
    g_srcs[pos] = __ldg(ei + e);
}

// ---------------- message pass: h[d] = x[d] + sum relu(x[src]+e) -----------
__global__ __launch_bounds__(96)
void msg_csr()
{
    int d = blockIdx.x;
    int t = threadIdx.x;
    if (t >= F4C) return;
    int beg = g_rowptr[d];
    int end = g_rowptr[d + 1];
    const float4* E = (const float4*)g_e;
    const float4* X = (const float4*)g_x;
    float4 acc = X[(long long)d * F4C + t];
    for (int j = beg; j < end; j++) {
        int s = __ldg(&g_srcs[j]);
        float4 ev = __ldcs(E + (long long)j * F4C + t);
        float4 xv = __ldg(X + (long long)s * F4C + t);
        acc.x += fmaxf(ev.x + xv.x, 0.f);
        acc.y += fmaxf(ev.y + xv.y, 0.f);
        acc.z += fmaxf(ev.z + xv.z, 0.f);
        acc.w += fmaxf(ev.w + xv.w, 0.f);
    }
    ((float4*)g_h)[(long long)d * F4C + t] = acc;
}

// ---------------- x := LN(x + relu(h2)) ------------------------------------
__global__ void ln_kernel(const float* __restrict__ g, const float* __restrict__ b)
{
    int warp = threadIdx.x >> 5;
    int lane = threadIdx.x & 31;
    int row  = blockIdx.x * 8 + warp;
    if (row >= NN) return;
    const float* xr = g_x + (long long)row * DD;
    const float* hr = g_h + (long long)row * DD;

    float v[10];
    float s = 0.f;
#pragma unroll
    for (int i = 0; i < 10; i++) {
        int j = lane + 32 * i;
        if (j < DD) { v[i] = xr[j] + fmaxf(hr[j], 0.f); s += v[i]; }
        else          v[i] = 0.f;
    }
#pragma unroll
    for (int o = 16; o; o >>= 1) s += __shfl_xor_sync(0xffffffffu, s, o);
    float mu = s * (1.f / DD);

    float vs = 0.f;
#pragma unroll
    for (int i = 0; i < 10; i++) {
        int j = lane + 32 * i;
        if (j < DD) { float d = v[i] - mu; vs += d * d; }
    }
#pragma unroll
    for (int o = 16; o; o >>= 1) vs += __shfl_xor_sync(0xffffffffu, vs, o);
    float rstd = rsqrtf(vs * (1.f / DD) + 1e-5f);

    float* xw = g_x + (long long)row * DD;
#pragma unroll
    for (int i = 0; i < 10; i++) {
        int j = lane + 32 * i;
        if (j < DD) xw[j] = (v[i] - mu) * rstd * g[j] + b[j];
    }
}

// ---------------- pooling ---------------------------------------------------
__global__ void zero_pool()
{
    int idx = blockIdx.x * 256 + threadIdx.x;
    if (idx < NG * DD) g_pool[idx] = 0.f;
    if (idx < NG)      g_cnt[idx]  = 0.f;
}
__global__ void pool_accum(const int* __restrict__ batch)
{
    int idx = blockIdx.x * 256 + threadIdx.x;
    if (idx >= NN * F4C) return;
    int n = idx / F4C;
    int c = idx - n * F4C;
    int bg = __ldg(batch + n);
    float4 xv = ((const float4*)g_x)[idx];
    float* p = g_pool + bg * DD + c * 4;
    atomicAdd(p + 0, xv.x);
    atomicAdd(p + 1, xv.y);
    atomicAdd(p + 2, xv.z);
    atomicAdd(p + 3, xv.w);
    if (c == 0) atomicAdd(&g_cnt[bg], 1.f);
}
__global__ void pool_div()
{
    int idx = blockIdx.x * 256 + threadIdx.x;
    if (idx < NG * DD) g_pool[idx] /= fmaxf(g_cnt[idx / DD], 1.f);
}
__global__ void small_gemm(const float* __restrict__ A, const float* __restrict__ W,
                           const float* __restrict__ bias, float* __restrict__ O,
                           int K, int Nout)
{
    int j = blockIdx.x * blockDim.x + threadIdx.x;
    int g = blockIdx.y;
    if (j >= Nout) return;
    float s = bias[j];
    const float* ar = A + g * K;
    for (int k = 0; k < K; k++)
        s = fmaf(__ldg(ar + k), __ldg(&W[k * Nout + j]), s);
    O[g * Nout + j] = s;
}

// ============================================================
extern "C" void kernel_launch(void* const* d_in, const int* in_sizes, int n_in,
                              void* d_out, int out_size)
{
    const int*   z       = (const int*)  d_in[0];
    const float* chir    = (const float*)d_in[1];
    const float* fc      = (const float*)d_in[2];
    const int*   ei      = (const int*)  d_in[3];
    const float* ea      = (const float*)d_in[4];
    const int*   batch   = (const int*)  d_in[5];
    const float* atom_emb= (const float*)d_in[6];
    const float* nap_W1  = (const float*)d_in[7];
    const float* nap_b1  = (const float*)d_in[8];
    const float* nap_W2  = (const float*)d_in[9];
    const float* nap_b2  = (const float*)d_in[10];
    const float* ee_W1   = (const float*)d_in[11];
    const float* ee_b1   = (const float*)d_in[12];
    const float* ee_W2   = (const float*)d_in[13];
    const float* ee_b2   = (const float*)d_in[14];
    const float* gine_W1 = (const float*)d_in[15];
    const float* gine_b1 = (const float*)d_in[16];
    const float* gine_W2 = (const float*)d_in[17];
    const float* gine_b2 = (const float*)d_in[18];
    const float* ln_g    = (const float*)d_in[19];
    const float* ln_b    = (const float*)d_in[20];
    const float* pool_W  = (const float*)d_in[21];
    const float* pool_b  = (const float*)d_in[22];
    const float* proj_W  = (const float*)d_in[23];
    const float* proj_b  = (const float*)d_in[24];

    float *px, *ph, *phid, *pe, *ppool, *ppool2;
    uint4 *pwb;
    int   *pslot;
    cudaGetSymbolAddress((void**)&px,    g_x);
    cudaGetSymbolAddress((void**)&ph,    g_h);
    cudaGetSymbolAddress((void**)&phid,  g_hid);
    cudaGetSymbolAddress((void**)&pe,    g_e);
    cudaGetSymbolAddress((void**)&pwb,   g_wb);
    cudaGetSymbolAddress((void**)&pslot, g_slot);
    cudaGetSymbolAddress((void**)&ppool, g_pool);
    cudaGetSymbolAddress((void**)&ppool2,g_pool2);

    cudaFuncSetAttribute(mma_gemm<A_NODE2, E_EMB,  false, 3>, cudaFuncAttributeMaxDynamicSharedMemorySize, SMEM_BYTES);
    cudaFuncSetAttribute(mma_gemm<A_EDGE3, E_BIAS, true,  2>, cudaFuncAttributeMaxDynamicSharedMemorySize, SMEM_BYTES);
    cudaFuncSetAttribute(mma_gemm<A_GMEM,  E_RELU, false, 3>, cudaFuncAttributeMaxDynamicSharedMemorySize, SMEM_BYTES);
    cudaFuncSetAttribute(mma_gemm<A_GMEM,  E_BIAS, false, 3>, cudaFuncAttributeMaxDynamicSharedMemorySize, SMEM_BYTES);

    const int gNode = (NN + 63) / 64;         // 782
    const int gEdge = NE / 64;                // 12500
    const int gNNv  = (NN * F4C + 255) / 256;
    const int gLN   = (NN + 7) / 8;
    const int gPool = (NG * DD + 255) / 256;
    const int gPrep = (NKT * NPADB * 8 + 255) / 256;
    const int gNNi  = (NN + 255) / 256;
    const int gNEi  = (NE + 255) / 256;
    const long long WSZ = (long long)NKT * NPADB * 8;

    // Launch order keeps node GEMM as 4th launch (ncu window).
    prep_w<<<gPrep, 256>>>(nap_W2, 0);                                  // 1
    prep_w<<<gPrep, 256>>>(ee_W2, 1);                                   // 2
    zero_cnt<<<gNNi, 256>>>();                                          // 3
    mma_gemm<A_NODE2, E_EMB, false, 3><<<gNode, 256, SMEM_BYTES>>>(     // 4 <- profiled
        nullptr, chir, fc, nap_W1, nap_b1,
        pwb + 0 * WSZ, nap_b2, atom_emb, z, nullptr, px, NN);

    // CSR build
    count_k<<<gNEi, 256>>>(ei);
    scan_k<<<1, 1024>>>();
    scatter_k<<<gNEi, 256>>>(ei);

    // remaining weight prep
    for (int i = 0; i < NL; i++) {
        prep_w<<<gPrep, 256>>>(gine_W1 + (long long)i * DD * DD, 2 + i);
        prep_w<<<gPrep, 256>>>(gine_W2 + (long long)i * DD * DD, 7 + i);
    }

    // edge emb (dst-sorted rows) — bf16x2 (drop hi*lo pass)
    mma_gemm<A_EDGE3, E_BIAS, true, 2><<<gEdge, 256, SMEM_BYTES>>>(
        nullptr, ea, nullptr, ee_W1, ee_b1,
        pwb + 1 * WSZ, ee_b2, nullptr, nullptr, pslot, pe, NE);

    // GINE layers
    for (int i = 0; i < NL; i++) {
        msg_csr<<<NN, 96>>>();
        mma_gemm<A_GMEM, E_RELU, false, 3><<<gNode, 256, SMEM_BYTES>>>(
            ph, nullptr, nullptr, nullptr, nullptr,
            pwb + (2 + i) * WSZ, gine_b1 + i * DD, nullptr, nullptr, nullptr, phid, NN);
        mma_gemm<A_GMEM, E_BIAS, false, 3><<<gNode, 256, SMEM_BYTES>>>(
            phid, nullptr, nullptr, nullptr, nullptr,
            pwb + (7 + i) * WSZ, gine_b2 + i * DD, nullptr, nullptr, nullptr, ph, NN);
        ln_kernel<<<gLN, 256>>>(ln_g + i * DD, ln_b + i * DD);
    }

    // pooling + projections
    zero_pool<<<gPool, 256>>>();
    pool_accum<<<gNNv, 256>>>(batch);
    pool_div<<<gPool, 256>>>();
    small_gemm<<<dim3(2, NG), 256>>>(ppool,  pool_W, pool_b, ppool2, DD, DD);
    small_gemm<<<dim3(3, NG), 256>>>(ppool2, proj_W, proj_b, (float*)d_out, DD, 600);
}

// round 17
// speedup vs baseline: 1.2912x; 1.0584x over previous
#include <cuda_runtime.h>
#include <cstdint>

// ---------------- problem constants ----------------
#define NN 50000
#define NE 800000
#define DD 300
#define NG 256
#define NL 5
#define F4C 75            // DD/4
#define NPADB 320         // n padded: 4 n-warps * 80

// ---------------- GEMM tiling: 64 x 320 tile, 256 thr, 2 CTAs/SM ----------
#define BKT 32
#define NKT 10
#define NT_W 10
#define MT_W 2
#define W_AH 0
#define W_AL 1280
#define W_B  2560
#define W_STAGE 12800
#define SMEM_BYTES (2*W_STAGE*4)   // 102400

// ---------------- scratch ----------------
__device__ float g_x   [NN * DD];
__device__ float g_h   [NN * DD];
__device__ float g_hid [NN * DD];
__device__ float g_e   [(long long)NE * DD];     // 960 MB (dst-sorted rows)
__device__ uint4 g_wb  [11 * NKT * NPADB * 8];   // bf16 frag-major weights
__device__ int   g_cnt_i [NN];
__device__ int   g_rowptr[NN + 1];
__device__ int   g_cursor[NN];
__device__ int   g_slot  [NE];
__device__ int   g_srcs  [NE];
__device__ float g_pool [NG * DD];
__device__ float g_pool2[NG * DD];
__device__ float g_cnt  [NG];

enum { A_GMEM = 0, A_NODE2 = 1, A_EDGE3 = 2 };
enum { E_BIAS = 0, E_RELU = 1, E_EMB = 2 };

// ---------------- helpers ----------------
__device__ __forceinline__ uint32_t smem_u32(const void* p) {
    uint32_t a;
    asm("{ .reg .u64 t; cvta.to.shared.u64 t, %1; cvt.u32.u64 %0, t; }" : "=r"(a) : "l"(p));
    return a;
}
__device__ __forceinline__ uint16_t bf16r(float f) {
    uint16_t u; asm("cvt.rn.bf16.f32 %0, %1;" : "=h"(u) : "f"(f)); return u;
}
__device__ __forceinline__ float bf2f(uint16_t u) {
    return __uint_as_float(((uint32_t)u) << 16);
}
__device__ __forceinline__ uint32_t packbf(uint16_t lo, uint16_t hi) {
    return ((uint32_t)hi << 16) | lo;
}
#define CP_ASYNC16(dst, src) \
    asm volatile("cp.async.ca.shared.global [%0], [%1], 16;" :: "r"(dst), "l"(src) : "memory")
#define CP_COMMIT()  asm volatile("cp.async.commit_group;" ::: "memory")
#define CP_WAIT0()   asm volatile("cp.async.wait_group 0;" ::: "memory")

__device__ __forceinline__ void mma_bf16(float* c, uint32_t a0, uint32_t a1, uint32_t a2,
                                         uint32_t a3, uint32_t b0, uint32_t b1) {
    asm volatile(
        "mma.sync.aligned.m16n8k16.row.col.f32.bf16.bf16.f32 "
        "{%0,%1,%2,%3}, {%4,%5,%6,%7}, {%8,%9}, {%0,%1,%2,%3};"
        : "+f"(c[0]), "+f"(c[1]), "+f"(c[2]), "+f"(c[3])
        : "r"(a0), "r"(a1), "r"(a2), "r"(a3), "r"(b0), "r"(b1));
}

// ---------------- weight prep: frag-major bf16 hi/lo chunks ----------------
__global__ void prep_w(const float* __restrict__ W, int mat)
{
    int idx = blockIdx.x * 256 + threadIdx.x;
    if (idx >= NKT * NPADB * 8) return;
    int kt = idx / (NPADB * 8);
    int r  = idx - kt * NPADB * 8;
    int n  = r >> 3;
    int slot = r & 7;
    int ks = ((slot ^ ((n & 1) * 4)) >> 2) & 1;
    int tg = slot & 3;
    int k0 = kt * 32 + ks * 16 + 2 * tg;

    float v[4];
#pragma unroll
    for (int j = 0; j < 4; j++) {
        int k = k0 + (j >> 1) * 8 + (j & 1);
        v[j] = (n < DD && k < DD) ? W[k * DD + n] : 0.f;
    }
    uint16_t h[4], l[4];
#pragma unroll
    for (int j = 0; j < 4; j++) {
        h[j] = bf16r(v[j]);
        l[j] = bf16r(v[j] - bf2f(h[j]));
    }
    g_wb[(long long)mat * NKT * NPADB * 8 + idx] =
        make_uint4(packbf(h[0],h[1]), packbf(h[2],h[3]), packbf(l[0],l[1]), packbf(l[2],l[3]));
}

// ---------------- A tile generation (64 rows, 256 threads) ------------------
template<int ASRC>
__device__ __forceinline__ void gen_a(uint4& oh, uint4& ol, int row0, int k0t, int M,
    const float* __restrict__ A, const float* __restrict__ s0,
    const float* __restrict__ s1, const float* __restrict__ aW1,
    const float* __restrict__ ab1, int tid)
{
    int row = tid >> 2, c4 = tid & 3;
    int mg = row0 + row;
    float f[8];
#pragma unroll
    for (int j = 0; j < 8; j++) f[j] = 0.f;
    if (mg < M) {
#pragma unroll
        for (int half = 0; half < 2; half++) {
            int kg = k0t + c4 * 8 + half * 4;
            if (kg < DD) {
                if (ASRC == A_GMEM) {
                    float4 v = *(const float4*)&A[(long long)mg * DD + kg];
                    f[half*4+0] = v.x; f[half*4+1] = v.y; f[half*4+2] = v.z; f[half*4+3] = v.w;
                } else if (ASRC == A_NODE2) {
                    float a0 = __ldg(&s0[mg]), a1 = __ldg(&s1[mg]);
                    float4 w0 = *(const float4*)&aW1[kg];
                    float4 w1 = *(const float4*)&aW1[DD + kg];
                    float4 bb = *(const float4*)&ab1[kg];
                    f[half*4+0] = fmaxf(a0*w0.x + a1*w1.x + bb.x, 0.f);
                    f[half*4+1] = fmaxf(a0*w0.y + a1*w1.y + bb.y, 0.f);
                    f[half*4+2] = fmaxf(a0*w0.z + a1*w1.z + bb.z, 0.f);
                    f[half*4+3] = fmaxf(a0*w0.w + a1*w1.w + bb.w, 0.f);
                } else {
                    float e0 = __ldg(&s0[mg*3+0]), e1 = __ldg(&s0[mg*3+1]), e2 = __ldg(&s0[mg*3+2]);
                    float4 w0 = *(const float4*)&aW1[kg];
                    float4 w1 = *(const float4*)&aW1[DD + kg];
                    float4 w2 = *(const float4*)&aW1[2*DD + kg];
                    float4 bb = *(const float4*)&ab1[kg];
                    f[half*4+0] = fmaxf(e0*w0.x + e1*w1.x + e2*w2.x + bb.x, 0.f);
                    f[half*4+1] = fmaxf(e0*w0.y + e1*w1.y + e2*w2.y + bb.y, 0.f);
                    f[half*4+2] = fmaxf(e0*w0.z + e1*w1.z + e2*w2.z + bb.z, 0.f);
                    f[half*4+3] = fmaxf(e0*w0.w + e1*w1.w + e2*w2.w + bb.w, 0.f);
                }
            }
        }
    }
    uint16_t h[8], l[8];
#pragma unroll
    for (int j = 0; j < 8; j++) {
        h[j] = bf16r(f[j]);
        l[j] = bf16r(f[j] - bf2f(h[j]));
    }
    oh = make_uint4(packbf(h[0],h[1]), packbf(h[2],h[3]), packbf(h[4],h[5]), packbf(h[6],h[7]));
    ol = make_uint4(packbf(l[0],l[1]), packbf(l[2],l[3]), packbf(l[4],l[5]), packbf(l[6],l[7]));
}

__device__ __forceinline__ void sts_a(uint32_t* sw, const uint4& oh, const uint4& ol, int tid)
{
    int row = tid >> 2, c4 = tid & 3;
    int w = row * 20 + c4 * 4;
    *(uint4*)(sw + W_AH + w) = oh;
    *(uint4*)(sw + W_AL + w) = ol;
}

__device__ __forceinline__ void issue_b(uint32_t* sw, const uint4* __restrict__ Bt,
                                        int kt, int tid)
{
    const uint4* src = Bt + (long long)kt * NPADB * 8;
    uint32_t dbase = smem_u32(sw + W_B);
#pragma unroll
    for (int i = 0; i < 10; i++) {
        int idx = tid + i * 256;
        CP_ASYNC16(dbase + idx * 16, src + idx);
    }
}

// ============================================================
// bf16 split mma.sync GEMM (R12-proven core).
// PASSES: 3 = full bf16x3; 2 = drop hi*lo; 1 = plain bf16 (hi*hi only).
// ============================================================
template<int ASRC, int EPI, bool PERM, int PASSES>
__global__ __launch_bounds__(256, 2)
void mma_gemm(const float* __restrict__ A,
              const float* __restrict__ s0, const float* __restrict__ s1,
              const float* __restrict__ aW1, const float* __restrict__ ab1,
              const uint4* __restrict__ Bt, const float* __restrict__ bias,
              const float* __restrict__ emb, const int* __restrict__ zidx,
              const int* __restrict__ perm,
              float* __restrict__ Out, int M)
{
    extern __shared__ uint32_t sw[];
    const int tid  = threadIdx.x;
    const int lane = tid & 31;
    const int wid  = tid >> 5;
    const int g    = lane >> 2;
    const int tg   = lane & 3;
    const int wm   = wid >> 2;
    const int wn   = wid & 3;
    const int row0 = blockIdx.x * 64;

    float acc[MT_W][NT_W][4];
#pragma unroll
    for (int mt = 0; mt < MT_W; mt++)
#pragma unroll
        for (int nt = 0; nt < NT_W; nt++)
#pragma unroll
            for (int i = 0; i < 4; i++) acc[mt][nt][i] = 0.f;

    {
        uint4 oh, ol;
        gen_a<ASRC>(oh, ol, row0, 0, M, A, s0, s1, aW1, ab1, tid);
        sts_a(sw, oh, ol, tid);
        issue_b(sw, Bt, 0, tid);
        CP_COMMIT();
        CP_WAIT0();
    }
    __syncthreads();

    for (int t = 0; t < NKT; t++) {
        uint32_t* cur = sw + (t & 1) * W_STAGE;
        uint32_t* nxt = sw + ((t & 1) ^ 1) * W_STAGE;
        const bool more = (t + 1 < NKT);

        uint4 oh, ol;
        if (more) {
            issue_b(nxt, Bt, t + 1, tid);
            CP_COMMIT();
            gen_a<ASRC>(oh, ol, row0, (t + 1) * BKT, M, A, s0, s1, aW1, ab1, tid);
        }

        const uint32_t* AH = cur + W_AH;
        const uint32_t* AL = cur + W_AL;
        const uint32_t* BB = cur + W_B;
#pragma unroll
        for (int ks = 0; ks < 2; ks++) {
            uint32_t aH[MT_W][4], aL[MT_W][4];
#pragma unroll
            for (int mt = 0; mt < MT_W; mt++) {
                int rbase = (wm * 32 + mt * 16 + g) * 20 + ks * 8 + tg;
                aH[mt][0] = AH[rbase];       aH[mt][1] = AH[rbase + 160];
                aH[mt][2] = AH[rbase + 4];   aH[mt][3] = AH[rbase + 164];
                if (PASSES >= 2) {
                    aL[mt][0] = AL[rbase];       aL[mt][1] = AL[rbase + 160];
                    aL[mt][2] = AL[rbase + 4];   aL[mt][3] = AL[rbase + 164];
                }
            }
            const int slot = (ks * 4 + tg) ^ ((g & 1) * 4);
#pragma unroll
            for (int nt = 0; nt < NT_W; nt++) {
                int n = wn * 80 + nt * 8 + g;
                uint4 b = *(const uint4*)(BB + (n * 8 + slot) * 4);
#pragma unroll
                for (int mt = 0; mt < MT_W; mt++) {
                    mma_bf16(acc[mt][nt], aH[mt][0], aH[mt][1], aH[mt][2], aH[mt][3], b.x, b.y);
                    if (PASSES >= 2)
                        mma_bf16(acc[mt][nt], aL[mt][0], aL[mt][1], aL[mt][2], aL[mt][3], b.x, b.y);
                    if (PASSES == 3)
                        mma_bf16(acc[mt][nt], aH[mt][0], aH[mt][1], aH[mt][2], aH[mt][3], b.z, b.w);
                }
            }
        }

        if (more) {
            sts_a(nxt, oh, ol, tid);
            CP_WAIT0();
        }
        __syncthreads();
    }

    // ---- epilogue ----
#pragma unroll
    for (int mt = 0; mt < MT_W; mt++) {
        int r0 = row0 + wm * 32 + mt * 16 + g;
        int r1 = r0 + 8;
        const float* er0 = nullptr;
        const float* er1 = nullptr;
        if (EPI == E_EMB) {
            if (r0 < M) er0 = emb + (long long)__ldg(&zidx[r0]) * DD;
            if (r1 < M) er1 = emb + (long long)__ldg(&zidx[r1]) * DD;
        }
        long long o0 = 0, o1 = 0;
        if (r0 < M) o0 = (long long)(PERM ? __ldg(&perm[r0]) : r0) * DD;
        if (r1 < M) o1 = (long long)(PERM ? __ldg(&perm[r1]) : r1) * DD;
#pragma unroll
        for (int nt = 0; nt < NT_W; nt++) {
            int col = wn * 80 + nt * 8 + tg * 2;
            if (col >= DD) continue;
            float2 bb = *(const float2*)&bias[col];
            if (r0 < M) {
                float2 o = make_float2(acc[mt][nt][0] + bb.x, acc[mt][nt][1] + bb.y);
                if (EPI == E_EMB) { float2 e = *(const float2*)&er0[col]; o.x += e.x; o.y += e.y; }
                if (EPI == E_RELU) { o.x = fmaxf(o.x, 0.f); o.y = fmaxf(o.y, 0.f); }
                *(float2*)&Out[o0 + col] = o;
            }
            if (r1 < M) {
                float2 o = make_float2(acc[mt][nt][2] + bb.x, acc[mt][nt][3] + bb.y);
                if (EPI == E_EMB) { float2 e = *(const float2*)&er1[col]; o.x += e.x; o.y += e.y; }
                if (EPI == E_RELU) { o.x = fmaxf(o.x, 0.f); o.y = fmaxf(o.y, 0.f); }
                *(float2*)&Out[o1 + col] = o;
            }
        }
    }
}

// ---------------- CSR build (R12-proven) -----------------------------------
__global__ void zero_cnt()
{
    int i = blockIdx.x * 256 + threadIdx.x;
    if (i < NN) g_cnt_i[i] = 0;
}
__global__ void count_k(const int* __restrict__ ei)
{
    int e = blockIdx.x * 256 + threadIdx.x;
    if (e < NE) atomicAdd(&g_cnt_i[__ldg(ei + NE + e)], 1);
}
__global__ void scan_k()
{
    __shared__ int sm[1024];
    __shared__ int carry;
    int t = threadIdx.x;
    if (t == 0) carry = 0;
    __syncthreads();
    for (int base = 0; base < NN; base += 1024) {
        int i = base + t;
        int v = (i < NN) ? g_cnt_i[i] : 0;
        sm[t] = v;
        __syncthreads();
        for (int off = 1; off < 1024; off <<= 1) {
            int u = (t >= off) ? sm[t - off] : 0;
            __syncthreads();
            sm[t] += u;
            __syncthreads();
        }
        int exc = sm[t] - v + carry;
        if (i < NN) { g_rowptr[i] = exc; g_cursor[i] = exc; }
        __syncthreads();
        if (t == 1023) carry += sm[1023];
        __syncthreads();
    }
    if (t == 0) g_rowptr[NN] = carry;
}
__global__ void scatter_k(const int* __restrict__ ei)
{
    int e = blockIdx.x * 256 + threadIdx.x;
    if (e >= NE) return;
    int d = __ldg(ei + NE + e);
    int pos = atomicAdd(&g_cursor[d], 1);
    g_slot[e] = pos;
    g_srcs[pos] = __ldg(ei + e);
}

// ---------------- message pass: h[d] = x[d] + sum relu(x[src]+e) -----------
__global__ __launch_bounds__(96)
void msg_csr()
{
    int d = blockIdx.x;
    int t = threadIdx.x;
    if (t >= F4C) return;
    int beg = g_rowptr[d];
    int end = g_rowptr[d + 1];
    const float4* E = (const float4*)g_e;
    const float4* X = (const float4*)g_x;
    float4 acc = X[(long long)d * F4C + t];
    for (int j = beg; j < end; j++) {
        int s = __ldg(&g_srcs[j]);
        float4 ev = __ldcs(E + (long long)j * F4C + t);
        float4 xv = __ldg(X + (long long)s * F4C + t);
        acc.x += fmaxf(ev.x + xv.x, 0.f);
        acc.y += fmaxf(ev.y + xv.y, 0.f);
        acc.z += fmaxf(ev.z + xv.z, 0.f);
        acc.w += fmaxf(ev.w + xv.w, 0.f);
    }
    ((float4*)g_h)[(long long)d * F4C + t] = acc;
}

// ---------------- x := LN(x + relu(h2)) ------------------------------------
__global__ void ln_kernel(const float* __restrict__ g, const float* __restrict__ b)
{
    int warp = threadIdx.x >> 5;
    int lane = threadIdx.x & 31;
    int row  = blockIdx.x * 8 + warp;
    if (row >= NN) return;
    const float* xr = g_x + (long long)row * DD;
    const float* hr = g_h + (long long)row * DD;

    float v[10];
    float s = 0.f;
#pragma unroll
    for (int i = 0; i < 10; i++) {
        int j = lane + 32 * i;
        if (j < DD) { v[i] = xr[j] + fmaxf(hr[j], 0.f); s += v[i]; }
        else          v[i] = 0.f;
    }
#pragma unroll
    for (int o = 16; o; o >>= 1) s += __shfl_xor_sync(0xffffffffu, s, o);
    float mu = s * (1.f / DD);

    float vs = 0.f;
#pragma unroll
    for (int i = 0; i < 10; i++) {
        int j = lane + 32 * i;
        if (j < DD) { float d = v[i] - mu; vs += d * d; }
    }
#pragma unroll
    for (int o = 16; o; o >>= 1) vs += __shfl_xor_sync(0xffffffffu, vs, o);
    float rstd = rsqrtf(vs * (1.f / DD) + 1e-5f);

    float* xw = g_x + (long long)row * DD;
#pragma unroll
    for (int i = 0; i < 10; i++) {
        int j = lane + 32 * i;
        if (j < DD) xw[j] = (v[i] - mu) * rstd * g[j] + b[j];
    }
}

// ---------------- pooling ---------------------------------------------------
__global__ void zero_pool()
{
    int idx = blockIdx.x * 256 + threadIdx.x;
    if (idx < NG * DD) g_pool[idx] = 0.f;
    if (idx < NG)      g_cnt[idx]  = 0.f;
}
__global__ void pool_accum(const int* __restrict__ batch)
{
    int idx = blockIdx.x * 256 + threadIdx.x;
    if (idx >= NN * F4C) return;
    int n = idx / F4C;
    int c = idx - n * F4C;
    int bg = __ldg(batch + n);
    float4 xv = ((const float4*)g_x)[idx];
    float* p = g_pool + bg * DD + c * 4;
    atomicAdd(p + 0, xv.x);
    atomicAdd(p + 1, xv.y);
    atomicAdd(p + 2, xv.z);
    atomicAdd(p + 3, xv.w);
    if (c == 0) atomicAdd(&g_cnt[bg], 1.f);
}
__global__ void pool_div()
{
    int idx = blockIdx.x * 256 + threadIdx.x;
    if (idx < NG * DD) g_pool[idx] /= fmaxf(g_cnt[idx / DD], 1.f);
}
__global__ void small_gemm(const float* __restrict__ A, const float* __restrict__ W,
                           const float* __restrict__ bias, float* __restrict__ O,
                           int K, int Nout)
{
    int j = blockIdx.x * blockDim.x + threadIdx.x;
    int g = blockIdx.y;
    if (j >= Nout) return;
    float s = bias[j];
    const float* ar = A + g * K;
    for (int k = 0; k < K; k++)
        s = fmaf(__ldg(ar + k), __ldg(&W[k * Nout + j]), s);
    O[g * Nout + j] = s;
}

// ============================================================
extern "C" void kernel_launch(void* const* d_in, const int* in_sizes, int n_in,
                              void* d_out, int out_size)
{
    const int*   z       = (const int*)  d_in[0];
    const float* chir    = (const float*)d_in[1];
    const float* fc      = (const float*)d_in[2];
    const int*   ei      = (const int*)  d_in[3];
    const float* ea      = (const float*)d_in[4];
    const int*   batch   = (const int*)  d_in[5];
    const float* atom_emb= (const float*)d_in[6];
    const float* nap_W1  = (const float*)d_in[7];
    const float* nap_b1  = (const float*)d_in[8];
    const float* nap_W2  = (const float*)d_in[9];
    const float* nap_b2  = (const float*)d_in[10];
    const float* ee_W1   = (const float*)d_in[11];
    const float* ee_b1   = (const float*)d_in[12];
    const float* ee_W2   = (const float*)d_in[13];
    const float* ee_b2   = (const float*)d_in[14];
    const float* gine_W1 = (const float*)d_in[15];
    const float* gine_b1 = (const float*)d_in[16];
    const float* gine_W2 = (const float*)d_in[17];
    const float* gine_b2 = (const float*)d_in[18];
    const float* ln_g    = (const float*)d_in[19];
    const float* ln_b    = (const float*)d_in[20];
    const float* pool_W  = (const float*)d_in[21];
    const float* pool_b  = (const float*)d_in[22];
    const float* proj_W  = (const float*)d_in[23];
    const float* proj_b  = (const float*)d_in[24];

    float *px, *ph, *phid, *pe, *ppool, *ppool2;
    uint4 *pwb;
    int   *pslot;
    cudaGetSymbolAddress((void**)&px,    g_x);
    cudaGetSymbolAddress((void**)&ph,    g_h);
    cudaGetSymbolAddress((void**)&phid,  g_hid);
    cudaGetSymbolAddress((void**)&pe,    g_e);
    cudaGetSymbolAddress((void**)&pwb,   g_wb);
    cudaGetSymbolAddress((void**)&pslot, g_slot);
    cudaGetSymbolAddress((void**)&ppool, g_pool);
    cudaGetSymbolAddress((void**)&ppool2,g_pool2);

    cudaFuncSetAttribute(mma_gemm<A_NODE2, E_EMB,  false, 3>, cudaFuncAttributeMaxDynamicSharedMemorySize, SMEM_BYTES);
    cudaFuncSetAttribute(mma_gemm<A_EDGE3, E_BIAS, true,  1>, cudaFuncAttributeMaxDynamicSharedMemorySize, SMEM_BYTES);
    cudaFuncSetAttribute(mma_gemm<A_GMEM,  E_RELU, false, 3>, cudaFuncAttributeMaxDynamicSharedMemorySize, SMEM_BYTES);
    cudaFuncSetAttribute(mma_gemm<A_GMEM,  E_BIAS, false, 3>, cudaFuncAttributeMaxDynamicSharedMemorySize, SMEM_BYTES);

    const int gNode = (NN + 63) / 64;         // 782
    const int gEdge = NE / 64;                // 12500
    const int gNNv  = (NN * F4C + 255) / 256;
    const int gLN   = (NN + 7) / 8;
    const int gPool = (NG * DD + 255) / 256;
    const int gPrep = (NKT * NPADB * 8 + 255) / 256;
    const int gNNi  = (NN + 255) / 256;
    const int gNEi  = (NE + 255) / 256;
    const long long WSZ = (long long)NKT * NPADB * 8;

    // Launch order keeps node GEMM as 4th launch (ncu window).
    prep_w<<<gPrep, 256>>>(nap_W2, 0);                                  // 1
    prep_w<<<gPrep, 256>>>(ee_W2, 1);                                   // 2
    zero_cnt<<<gNNi, 256>>>();                                          // 3
    mma_gemm<A_NODE2, E_EMB, false, 3><<<gNode, 256, SMEM_BYTES>>>(     // 4 <- profiled
        nullptr, chir, fc, nap_W1, nap_b1,
        pwb + 0 * WSZ, nap_b2, atom_emb, z, nullptr, px, NN);

    // CSR build
    count_k<<<gNEi, 256>>>(ei);
    scan_k<<<1, 1024>>>();
    scatter_k<<<gNEi, 256>>>(ei);

    // remaining weight prep
    for (int i = 0; i < NL; i++) {
        prep_w<<<gPrep, 256>>>(gine_W1 + (long long)i * DD * DD, 2 + i);
        prep_w<<<gPrep, 256>>>(gine_W2 + (long long)i * DD * DD, 7 + i);
    }

    // edge emb (dst-sorted rows) — single-pass bf16
    mma_gemm<A_EDGE3, E_BIAS, true, 1><<<gEdge, 256, SMEM_BYTES>>>(
        nullptr, ea, nullptr, ee_W1, ee_b1,
        pwb + 1 * WSZ, ee_b2, nullptr, nullptr, pslot, pe, NE);

    // GINE layers
    for (int i = 0; i < NL; i++) {
        msg_csr<<<NN, 96>>>();
        mma_gemm<A_GMEM, E_RELU, false, 3><<<gNode, 256, SMEM_BYTES>>>(
            ph, nullptr, nullptr, nullptr, nullptr,
            pwb + (2 + i) * WSZ, gine_b1 + i * DD, nullptr, nullptr, nullptr, phid, NN);
        mma_gemm<A_GMEM, E_BIAS, false, 3><<<gNode, 256, SMEM_BYTES>>>(
            phid, nullptr, nullptr, nullptr, nullptr,
            pwb + (7 + i) * WSZ, gine_b2 + i * DD, nullptr, nullptr, nullptr, ph, NN);
        ln_kernel<<<gLN, 256>>>(ln_g + i * DD, ln_b + i * DD);
    }

    // pooling + projections
    zero_pool<<<gPool, 256>>>();
    pool_accum<<<gNNv, 256>>>(batch);
    pool_div<<<gPool, 256>>>();
    small_gemm<<<dim3(2, NG), 256>>>(ppool,  pool_W, pool_b, ppool2, DD, DD);
    small_gemm<<<dim3(3, NG), 256>>>(ppool2, proj_W, proj_b, (float*)d_out, DD, 600);
}